// round 15
// baseline (speedup 1.0000x reference)
#include <cuda_runtime.h>
#include <cuda_fp16.h>
#include <math.h>
#include <stdint.h>

#define BATCH 8
#define SEQ   2048
#define DIM   512
#define MTOT  (BATCH*SEQ)        // 16384

// ===========================================================================
// Scratch memory (single __device__ array; no allocation anywhere)
// ===========================================================================
#define SZ_X ((size_t)MTOT * DIM)                     // 8,388,608 elems
static const size_t O_XH   = 0;                                 // fp16 SZ_X
static const size_t O_WH   = O_XH  + SZ_X * 2;                  // fp16 3*DIM*DIM
static const size_t O_QKVH = O_WH  + (size_t)3 * DIM * DIM * 2; // fp16 3*SZ_X
static const size_t O_VT   = O_QKVH + (size_t)3 * SZ_X * 2;     // fp16 SZ_X (V^T)
static const size_t O_SH   = O_VT  + SZ_X * 2;                  // fp16 B*S*S
static const size_t SCRATCH_TOTAL = O_SH + (size_t)BATCH * SEQ * SEQ * 2;

__device__ __align__(1024) unsigned char g_scratch[SCRATCH_TOTAL];

// ===========================================================================
// PTX helpers (arch-agnostic: cp.async / ldmatrix / mma.sync only)
// ===========================================================================
__device__ __forceinline__ uint32_t smem_u32(const void* p) {
    uint32_t a;
    asm("{ .reg .u64 t; cvta.to.shared.u64 t, %1; cvt.u32.u64 %0, t; }"
        : "=r"(a) : "l"(p));
    return a;
}

#define SWZ128(x) ((x) ^ (((x) >> 3) & 0x70))

__device__ __forceinline__ void cp16(uint32_t dst, const void* src) {
    asm volatile("cp.async.cg.shared.global [%0], [%1], 16;\n"
                 :: "r"(dst), "l"(src));
}
__device__ __forceinline__ void cp_commit() {
    asm volatile("cp.async.commit_group;\n" ::: "memory");
}
template <int N> __device__ __forceinline__ void cp_wait() {
    asm volatile("cp.async.wait_group %0;\n" :: "n"(N) : "memory");
}

__device__ __forceinline__ void ldm_x4(uint32_t* r, uint32_t addr) {
    asm volatile("ldmatrix.sync.aligned.m8n8.x4.shared.b16 {%0,%1,%2,%3}, [%4];"
                 : "=r"(r[0]), "=r"(r[1]), "=r"(r[2]), "=r"(r[3]) : "r"(addr));
}

__device__ __forceinline__ void mma_f16(float* c, const uint32_t* a,
                                        uint32_t b0, uint32_t b1) {
    asm volatile("mma.sync.aligned.m16n8k16.row.col.f32.f16.f16.f32 "
                 "{%0,%1,%2,%3}, {%4,%5,%6,%7}, {%8,%9}, {%0,%1,%2,%3};"
                 : "+f"(c[0]), "+f"(c[1]), "+f"(c[2]), "+f"(c[3])
                 : "r"(a[0]), "r"(a[1]), "r"(a[2]), "r"(a[3]), "r"(b0), "r"(b1));
}

// ===========================================================================
// Single-term HMMA GEMM:  C = alpha * A@B^T   (fp16 NT, fp32 accum)
// CTA 128x128, BK=64, 256 threads, 8 warps x (32M x 64N) tiles,
// 3-stage cp.async pipeline (3 x 32 KB), one barrier per k-iter, 2 CTAs/SM.
// Addressing fully hoisted:
//   SWZ128(rowoff + koff) == rowoff + (koff ^ xv)  for rowoff%128==0, koff<128,
//   xv = (lane_row & 7) * 16   -> all ldmatrix addrs are base+const adds.
//   Global cp.async pointers advanced by +64 elems/stage (no per-stage IMAD).
// Epilogue: fp32*alpha if Ch==null, else fp16 (alpha applied).
// ===========================================================================
#define ST_BYTES 32768u
#define SMEM_GEMM (3 * 32768 + 1024)

__global__ __launch_bounds__(256, 2)
void hgemm1(const __half* __restrict__ A,
            const __half* __restrict__ B,
            float* __restrict__ C,
            __half* __restrict__ Ch,
            int ldA, int ldB, int ldC, int kTiles,
            size_t sA, size_t sB, size_t sC, float alpha)
{
    extern __shared__ char smem_raw[];
    const uint32_t sbase = (smem_u32(smem_raw) + 1023u) & ~1023u;

    const int tid  = threadIdx.x;
    const int wid  = tid >> 5;
    const int lane = tid & 31;
    const int wm   = wid & 3;      // 4 M-warps -> 32 rows each
    const int wn   = wid >> 2;     // 2 N-warps -> 64 cols each

    const int row0 = blockIdx.y * 128;
    const int col0 = blockIdx.x * 128;

    // ---- hoisted global load pointers (advance +64 per stage) ----
    const int lr = tid >> 3;            // 0..31 (base row among 128, step 32 via q)
    const int lc = tid & 7;             // 16B chunk
    const __half* gA = A + (size_t)blockIdx.z * sA + (size_t)(row0 + lr) * ldA + lc * 8;
    const __half* gB = B + (size_t)blockIdx.z * sB + (size_t)(col0 + lr) * ldB + lc * 8;
    const size_t strideA32 = (size_t)32 * ldA;
    const size_t strideB32 = (size_t)32 * ldB;
    // smem dst offset: q*32 row step is 0 mod 8 -> swizzle XOR constant across q
    const uint32_t d0 = (uint32_t)(lr * 128) + ((uint32_t)(lc * 16) ^ ((uint32_t)(lr & 7) * 16));

    float acc[2][8][4];
    #pragma unroll
    for (int mt = 0; mt < 2; mt++)
        #pragma unroll
        for (int j = 0; j < 8; j++)
            #pragma unroll
            for (int q = 0; q < 4; q++) acc[mt][j][q] = 0.f;

    auto load_stage = [&](int t) {
        const uint32_t st = sbase + (uint32_t)(t % 3) * ST_BYTES;
        #pragma unroll
        for (int q = 0; q < 4; q++) {
            cp16(st +          d0 + (uint32_t)q * 4096u, gA + q * strideA32);
            cp16(st + 16384u + d0 + (uint32_t)q * 4096u, gB + q * strideB32);
        }
        cp_commit();
        gA += 64;
        gB += 64;
    };

    load_stage(0);
    if (kTiles > 1) load_stage(1);

    // ---- hoisted ldmatrix addressing ----
    const uint32_t lrow = (uint32_t)(lane & 15);
    const uint32_t lcol = (uint32_t)((lane >> 4) * 16);
    const uint32_t xv   = (lrow & 7u) * 16u;           // swizzle XOR value
    const uint32_t lx   = lcol ^ (xv & 0x10u);         // bit 4 part
    const uint32_t xh   = xv & 0x60u;                  // bits 5-6 part
    uint32_t kx[4];
    #pragma unroll
    for (int k16 = 0; k16 < 4; k16++)
        kx[k16] = ((uint32_t)(k16 * 32) ^ xh) + lx;    // disjoint bits: + == |
    const uint32_t rowA = ((uint32_t)(wm * 32) + lrow) * 128u;   // + mt*2048
    const uint32_t rowB = ((uint32_t)(wn * 64) + lrow) * 128u;   // + ng*2048

    for (int t = 0; t < kTiles; t++) {
        if (t + 1 < kTiles) cp_wait<1>(); else cp_wait<0>();
        __syncthreads();
        if (t + 2 < kTiles) load_stage(t + 2);

        const uint32_t st = sbase + (uint32_t)(t % 3) * ST_BYTES;
        const uint32_t As = st + rowA;
        const uint32_t Bs = st + 16384u + rowB;

        #pragma unroll
        for (int k16 = 0; k16 < 4; k16++) {
            const uint32_t ko = kx[k16];
            uint32_t a[2][4];
            #pragma unroll
            for (int mt = 0; mt < 2; mt++)
                ldm_x4(a[mt], As + (uint32_t)(mt * 2048) + ko);
            uint32_t b[4][4];
            #pragma unroll
            for (int ng = 0; ng < 4; ng++)
                ldm_x4(b[ng], Bs + (uint32_t)(ng * 2048) + ko);
            #pragma unroll
            for (int mt = 0; mt < 2; mt++)
                #pragma unroll
                for (int j = 0; j < 8; j++) {
                    const int ng = j >> 1;
                    mma_f16(acc[mt][j], a[mt], b[ng][(j & 1) ? 1 : 0], b[ng][(j & 1) ? 3 : 2]);
                }
        }
    }

    const int er = lane >> 2;
    const int ec = (lane & 3) * 2;
    if (Ch) {
        Ch += (size_t)blockIdx.z * sC;
        #pragma unroll
        for (int mt = 0; mt < 2; mt++) {
            const int rb = row0 + wm * 32 + mt * 16 + er;
            #pragma unroll
            for (int j = 0; j < 8; j++) {
                const int cb = col0 + wn * 64 + j * 8 + ec;
                __half2 H0, H1;
                H0.x = __float2half(alpha * acc[mt][j][0]);
                H0.y = __float2half(alpha * acc[mt][j][1]);
                H1.x = __float2half(alpha * acc[mt][j][2]);
                H1.y = __float2half(alpha * acc[mt][j][3]);
                *(__half2*)(Ch + (size_t)rb * ldC + cb)       = H0;
                *(__half2*)(Ch + (size_t)(rb + 8) * ldC + cb) = H1;
            }
        }
    } else {
        C += (size_t)blockIdx.z * sC;
        #pragma unroll
        for (int mt = 0; mt < 2; mt++) {
            const int rb = row0 + wm * 32 + mt * 16 + er;
            #pragma unroll
            for (int j = 0; j < 8; j++) {
                const int cb = col0 + wn * 64 + j * 8 + ec;
                *(float2*)(C + (size_t)rb * ldC + cb) =
                    make_float2(alpha * acc[mt][j][0], alpha * acc[mt][j][1]);
                *(float2*)(C + (size_t)(rb + 8) * ldC + cb) =
                    make_float2(alpha * acc[mt][j][2], alpha * acc[mt][j][3]);
            }
        }
    }
}

// ===========================================================================
// Fused fp32 -> fp16 convert for x and the 3 weight matrices (ONE launch).
// ===========================================================================
#define NX4 (SZ_X / 4)                     // 2,097,152 float4's of x
#define W4  ((size_t)DIM * DIM / 4)        // 65,536 float4's per weight

__global__ __launch_bounds__(256)
void cvt_all(const float* __restrict__ x,
             const float* __restrict__ Wq,
             const float* __restrict__ Wk,
             const float* __restrict__ Wv,
             __half* __restrict__ xh, __half* __restrict__ wh)
{
    size_t i = (size_t)blockIdx.x * 256 + threadIdx.x;
    const float* src;
    __half* dst;
    size_t off;
    if (i < NX4) {
        src = x;  dst = xh;  off = i;
    } else {
        size_t j = i - NX4;
        size_t w = j / W4;
        off = j - w * W4;
        src = (w == 0) ? Wq : (w == 1) ? Wk : Wv;
        dst = wh + w * DIM * DIM;
    }
    float4 v = ((const float4*)src)[off];
    __half2 H0, H1;
    H0.x = __float2half(v.x); H0.y = __float2half(v.y);
    H1.x = __float2half(v.z); H1.y = __float2half(v.w);
    ((__half2*)dst)[2 * off + 0] = H0;
    ((__half2*)dst)[2 * off + 1] = H1;
}

// ===========================================================================
// fp16 [b,s,d] -> fp16 [b,d,s] transpose (64x64 tiles), grid.z = batch
// ===========================================================================
__global__ __launch_bounds__(256)
void transpose_h(const __half* __restrict__ src, __half* __restrict__ dst)
{
    __shared__ __half t[64][65];
    const int b  = blockIdx.z;
    const int s0 = blockIdx.x * 64, d0 = blockIdx.y * 64;
    const int tid = threadIdx.x;
    src += (size_t)b * SEQ * DIM;
    dst += (size_t)b * DIM * SEQ;

    #pragma unroll
    for (int q = 0; q < 8; q++) {
        int i = tid + q * 256;
        int row = i >> 5, cp = i & 31;
        __half2 v = *(const __half2*)(src + (size_t)(s0 + row) * DIM + d0 + cp * 2);
        t[row][cp * 2 + 0] = v.x;
        t[row][cp * 2 + 1] = v.y;
    }
    __syncthreads();
    #pragma unroll
    for (int q = 0; q < 8; q++) {
        int i = tid + q * 256;
        int drow = i >> 5, sp = i & 31;
        __half2 o;
        o.x = t[sp * 2 + 0][drow];
        o.y = t[sp * 2 + 1][drow];
        *(__half2*)(dst + (size_t)(d0 + drow) * SEQ + s0 + sp * 2) = o;
    }
}

// ===========================================================================
// Row softmax, in place on fp16 scores (fp32 math in registers)
// ===========================================================================
__global__ __launch_bounds__(256)
void softmax_h16(__half* __restrict__ S)
{
    __shared__ float red_m[8];
    __shared__ float red_s[8];
    const size_t base = (size_t)blockIdx.x * SEQ;
    const int tid  = threadIdx.x;
    const int wid  = tid >> 5;
    const int lane = tid & 31;

    uint4 raw = ((const uint4*)(S + base))[tid];
    __half2 h[4];
    h[0] = *(__half2*)&raw.x; h[1] = *(__half2*)&raw.y;
    h[2] = *(__half2*)&raw.z; h[3] = *(__half2*)&raw.w;
    float v[8];
    #pragma unroll
    for (int i = 0; i < 4; i++) {
        v[2 * i + 0] = __half2float(h[i].x);
        v[2 * i + 1] = __half2float(h[i].y);
    }

    float m = v[0];
    #pragma unroll
    for (int i = 1; i < 8; i++) m = fmaxf(m, v[i]);
    #pragma unroll
    for (int o = 16; o > 0; o >>= 1) m = fmaxf(m, __shfl_xor_sync(~0u, m, o));
    if (lane == 0) red_m[wid] = m;
    __syncthreads();
    m = red_m[0];
    #pragma unroll
    for (int i = 1; i < 8; i++) m = fmaxf(m, red_m[i]);

    float s = 0.f;
    #pragma unroll
    for (int i = 0; i < 8; i++) { v[i] = __expf(v[i] - m); s += v[i]; }
    #pragma unroll
    for (int o = 16; o > 0; o >>= 1) s += __shfl_xor_sync(~0u, s, o);
    if (lane == 0) red_s[wid] = s;
    __syncthreads();
    s = red_s[0];
    #pragma unroll
    for (int i = 1; i < 8; i++) s += red_s[i];
    const float inv = 1.f / s;

    #pragma unroll
    for (int i = 0; i < 4; i++) {
        h[i].x = __float2half(v[2 * i + 0] * inv);
        h[i].y = __float2half(v[2 * i + 1] * inv);
    }
    uint4 outw;
    outw.x = *(uint32_t*)&h[0]; outw.y = *(uint32_t*)&h[1];
    outw.z = *(uint32_t*)&h[2]; outw.w = *(uint32_t*)&h[3];
    ((uint4*)(S + base))[tid] = outw;
}

// ===========================================================================
extern "C" void kernel_launch(void* const* d_in, const int* in_sizes, int n_in,
                              void* d_out, int out_size)
{
    const float* x  = (const float*)d_in[0];
    const float* Wq = (const float*)d_in[1];
    const float* Wk = (const float*)d_in[2];
    const float* Wv = (const float*)d_in[3];
    float* out = (float*)d_out;

    cudaFuncSetAttribute(hgemm1, cudaFuncAttributeMaxDynamicSharedMemorySize, SMEM_GEMM);

    unsigned char* base;
    cudaGetSymbolAddress((void**)&base, g_scratch);

    __half* xh   = (__half*)(base + O_XH);
    __half* wh   = (__half*)(base + O_WH);
    __half* qkvh = (__half*)(base + O_QKVH);
    __half* vt   = (__half*)(base + O_VT);
    __half* sh   = (__half*)(base + O_SH);

    const float scale = 0.044194173824159216f;   // 1/sqrt(512)

    // launch 0: convert x + Wq + Wk + Wv to fp16 (single fused launch)
    {
        const unsigned total4 = (unsigned)(NX4 + 3 * W4);
        cvt_all<<<total4 / 256, 256>>>(x, Wq, Wk, Wv, xh, wh);
    }

    // launch 1: QKV projections, fp16 epilogue (grid.z batches the 3 weights)
    {
        dim3 g(DIM / 128, MTOT / 128, 3);
        hgemm1<<<g, 256, SMEM_GEMM>>>(xh, wh, nullptr, qkvh,
                                      DIM, DIM, DIM, DIM / 64,
                                      0, (size_t)DIM * DIM, SZ_X, 1.0f);
    }

    // launch 2: transpose V -> V^T
    {
        dim3 g(SEQ / 64, DIM / 64, BATCH);
        transpose_h<<<g, 256>>>(qkvh + 2 * SZ_X, vt);
    }

    // launch 3: scores = Q @ K^T * scale, written directly as fp16
    {
        dim3 g(SEQ / 128, SEQ / 128, BATCH);
        hgemm1<<<g, 256, SMEM_GEMM>>>(qkvh, qkvh + SZ_X, nullptr, sh,
                                      DIM, DIM, SEQ, DIM / 64,
                                      (size_t)SEQ * DIM, (size_t)SEQ * DIM,
                                      (size_t)SEQ * SEQ, scale);
    }

    // launch 4: softmax in place on fp16 scores
    softmax_h16<<<BATCH * SEQ, 256>>>(sh);

    // launch 5: out = attn @ V  (fp32 epilogue)  <- ncu -s 5 -c 1 target
    {
        dim3 g(DIM / 128, SEQ / 128, BATCH);
        hgemm1<<<g, 256, SMEM_GEMM>>>(sh, vt, out, nullptr,
                                      SEQ, SEQ, DIM, SEQ / 64,
                                      (size_t)SEQ * SEQ, (size_t)DIM * SEQ,
                                      (size_t)SEQ * DIM, 1.0f);
    }
}

// round 16
// speedup vs baseline: 1.0132x; 1.0132x over previous
#include <cuda_runtime.h>
#include <cuda_fp16.h>
#include <math.h>
#include <stdint.h>

#define BATCH 8
#define SEQ   2048
#define DIM   512
#define MTOT  (BATCH*SEQ)        // 16384

// ===========================================================================
// Scratch memory (single __device__ array; no allocation anywhere)
// ===========================================================================
#define SZ_X ((size_t)MTOT * DIM)                     // 8,388,608 elems
static const size_t O_XH   = 0;                                 // fp16 SZ_X
static const size_t O_WH   = O_XH  + SZ_X * 2;                  // fp16 3*DIM*DIM
static const size_t O_QKVH = O_WH  + (size_t)3 * DIM * DIM * 2; // fp16 3*SZ_X
static const size_t O_VT   = O_QKVH + (size_t)3 * SZ_X * 2;     // fp16 SZ_X (V^T)
static const size_t O_SH   = O_VT  + SZ_X * 2;                  // fp16 B*S*S
static const size_t SCRATCH_TOTAL = O_SH + (size_t)BATCH * SEQ * SEQ * 2;

__device__ __align__(1024) unsigned char g_scratch[SCRATCH_TOTAL];

// ===========================================================================
// PTX helpers (arch-agnostic: cp.async / ldmatrix / mma.sync only)
// ===========================================================================
__device__ __forceinline__ uint32_t smem_u32(const void* p) {
    uint32_t a;
    asm("{ .reg .u64 t; cvta.to.shared.u64 t, %1; cvt.u32.u64 %0, t; }"
        : "=r"(a) : "l"(p));
    return a;
}

#define SWZ128(x) ((x) ^ (((x) >> 3) & 0x70))

__device__ __forceinline__ void cp16(uint32_t dst, const void* src) {
    asm volatile("cp.async.cg.shared.global [%0], [%1], 16;\n"
                 :: "r"(dst), "l"(src));
}
__device__ __forceinline__ void cp_commit() {
    asm volatile("cp.async.commit_group;\n" ::: "memory");
}
template <int N> __device__ __forceinline__ void cp_wait() {
    asm volatile("cp.async.wait_group %0;\n" :: "n"(N) : "memory");
}

__device__ __forceinline__ void ldm_x4(uint32_t* r, uint32_t addr) {
    asm volatile("ldmatrix.sync.aligned.m8n8.x4.shared.b16 {%0,%1,%2,%3}, [%4];"
                 : "=r"(r[0]), "=r"(r[1]), "=r"(r[2]), "=r"(r[3]) : "r"(addr));
}

__device__ __forceinline__ void mma_f16(float* c, const uint32_t* a,
                                        uint32_t b0, uint32_t b1) {
    asm volatile("mma.sync.aligned.m16n8k16.row.col.f32.f16.f16.f32 "
                 "{%0,%1,%2,%3}, {%4,%5,%6,%7}, {%8,%9}, {%0,%1,%2,%3};"
                 : "+f"(c[0]), "+f"(c[1]), "+f"(c[2]), "+f"(c[3])
                 : "r"(a[0]), "r"(a[1]), "r"(a[2]), "r"(a[3]), "r"(b0), "r"(b1));
}

// ===========================================================================
// Single-term HMMA GEMM:  C = alpha * A@B^T   (fp16 NT, fp32 accum)
// CTA 128x128, BK=64, 256 threads, 8 warps x (32M x 64N) tiles,
// 3-stage cp.async pipeline (3 x 32 KB), ONE barrier per k-iter, 2 CTAs/SM.
// (R12 champion configuration, restored verbatim.)
// Epilogue: fp32*alpha if Ch==null, else fp16 (alpha applied).
// ===========================================================================
#define ST_BYTES 32768u
#define SMEM_GEMM (3 * 32768 + 1024)

__global__ __launch_bounds__(256, 2)
void hgemm1(const __half* __restrict__ A,
            const __half* __restrict__ B,
            float* __restrict__ C,
            __half* __restrict__ Ch,
            int ldA, int ldB, int ldC, int kTiles,
            size_t sA, size_t sB, size_t sC, float alpha)
{
    extern __shared__ char smem_raw[];
    const uint32_t sbase = (smem_u32(smem_raw) + 1023u) & ~1023u;

    const int tid  = threadIdx.x;
    const int wid  = tid >> 5;
    const int lane = tid & 31;
    const int wm   = wid & 3;      // 4 M-warps -> 32 rows each
    const int wn   = wid >> 2;     // 2 N-warps -> 64 cols each

    const int row0 = blockIdx.y * 128;
    const int col0 = blockIdx.x * 128;

    A += (size_t)blockIdx.z * sA;
    B += (size_t)blockIdx.z * sB;

    float acc[2][8][4];
    #pragma unroll
    for (int mt = 0; mt < 2; mt++)
        #pragma unroll
        for (int j = 0; j < 8; j++)
            #pragma unroll
            for (int q = 0; q < 4; q++) acc[mt][j][q] = 0.f;

    auto load_stage = [&](int t) {
        const int kk = t * 64;
        const uint32_t st = sbase + (uint32_t)(t % 3) * ST_BYTES;
        #pragma unroll
        for (int q = 0; q < 4; q++) {
            int idx = tid + q * 256;
            int rr = idx >> 3, cc = idx & 7;
            uint32_t d = SWZ128((uint32_t)(rr * 128 + cc * 16));
            cp16(st +          d, A + (size_t)(row0 + rr) * ldA + kk + cc * 8);
            cp16(st + 16384u + d, B + (size_t)(col0 + rr) * ldB + kk + cc * 8);
        }
        cp_commit();
    };

    load_stage(0);
    if (kTiles > 1) load_stage(1);

    const uint32_t lrow = (uint32_t)(lane & 15);
    const uint32_t lcol = (uint32_t)((lane >> 4) * 16);

    for (int t = 0; t < kTiles; t++) {
        if (t + 1 < kTiles) cp_wait<1>(); else cp_wait<0>();
        __syncthreads();
        // stage t resident; buffer (t+2)%3 free (compute t-1 done by barrier)
        if (t + 2 < kTiles) load_stage(t + 2);

        const uint32_t st = sbase + (uint32_t)(t % 3) * ST_BYTES;
        const uint32_t As = st;
        const uint32_t Bs = st + 16384u;

        #pragma unroll
        for (int k16 = 0; k16 < 4; k16++) {
            const uint32_t koff = (uint32_t)(k16 * 32) + lcol;
            uint32_t a[2][4];
            #pragma unroll
            for (int mt = 0; mt < 2; mt++)
                ldm_x4(a[mt], As + SWZ128((uint32_t)((wm * 32 + mt * 16 + lrow) * 128) + koff));
            uint32_t b[4][4];
            #pragma unroll
            for (int ng = 0; ng < 4; ng++)
                ldm_x4(b[ng], Bs + SWZ128((uint32_t)((wn * 64 + ng * 16 + lrow) * 128) + koff));
            #pragma unroll
            for (int mt = 0; mt < 2; mt++)
                #pragma unroll
                for (int j = 0; j < 8; j++) {
                    const int ng = j >> 1;
                    mma_f16(acc[mt][j], a[mt], b[ng][(j & 1) ? 1 : 0], b[ng][(j & 1) ? 3 : 2]);
                }
        }
    }

    const int er = lane >> 2;
    const int ec = (lane & 3) * 2;
    if (Ch) {
        Ch += (size_t)blockIdx.z * sC;
        #pragma unroll
        for (int mt = 0; mt < 2; mt++) {
            const int rb = row0 + wm * 32 + mt * 16 + er;
            #pragma unroll
            for (int j = 0; j < 8; j++) {
                const int cb = col0 + wn * 64 + j * 8 + ec;
                __half2 H0, H1;
                H0.x = __float2half(alpha * acc[mt][j][0]);
                H0.y = __float2half(alpha * acc[mt][j][1]);
                H1.x = __float2half(alpha * acc[mt][j][2]);
                H1.y = __float2half(alpha * acc[mt][j][3]);
                *(__half2*)(Ch + (size_t)rb * ldC + cb)       = H0;
                *(__half2*)(Ch + (size_t)(rb + 8) * ldC + cb) = H1;
            }
        }
    } else {
        C += (size_t)blockIdx.z * sC;
        #pragma unroll
        for (int mt = 0; mt < 2; mt++) {
            const int rb = row0 + wm * 32 + mt * 16 + er;
            #pragma unroll
            for (int j = 0; j < 8; j++) {
                const int cb = col0 + wn * 64 + j * 8 + ec;
                *(float2*)(C + (size_t)rb * ldC + cb) =
                    make_float2(alpha * acc[mt][j][0], alpha * acc[mt][j][1]);
                *(float2*)(C + (size_t)(rb + 8) * ldC + cb) =
                    make_float2(alpha * acc[mt][j][2], alpha * acc[mt][j][3]);
            }
        }
    }
}

// ===========================================================================
// Fused fp32 -> fp16 convert for x and the 3 weight matrices (ONE launch,
// 2 float4's per thread).
// ===========================================================================
#define NX4 (SZ_X / 4)                     // 2,097,152 float4's of x
#define W4  ((size_t)DIM * DIM / 4)        // 65,536 float4's per weight
#define CVT_TOTAL4 (NX4 + 3 * W4)          // 2,293,760 (divisible by 512)

__global__ __launch_bounds__(256)
void cvt_all(const float* __restrict__ x,
             const float* __restrict__ Wq,
             const float* __restrict__ Wk,
             const float* __restrict__ Wv,
             __half* __restrict__ xh, __half* __restrict__ wh)
{
    const size_t base = (size_t)blockIdx.x * 512 + threadIdx.x;
    #pragma unroll
    for (int r = 0; r < 2; r++) {
        size_t i = base + (size_t)r * 256;
        const float* src;
        __half* dst;
        size_t off;
        if (i < NX4) {
            src = x;  dst = xh;  off = i;
        } else {
            size_t j = i - NX4;
            size_t w = j / W4;
            off = j - w * W4;
            src = (w == 0) ? Wq : (w == 1) ? Wk : Wv;
            dst = wh + w * DIM * DIM;
        }
        float4 v = ((const float4*)src)[off];
        __half2 H0, H1;
        H0.x = __float2half(v.x); H0.y = __float2half(v.y);
        H1.x = __float2half(v.z); H1.y = __float2half(v.w);
        ((__half2*)dst)[2 * off + 0] = H0;
        ((__half2*)dst)[2 * off + 1] = H1;
    }
}

// ===========================================================================
// fp16 [b,s,d] -> fp16 [b,d,s] transpose (64x64 tiles), float4 I/O
// ===========================================================================
__global__ __launch_bounds__(256)
void transpose_h(const __half* __restrict__ src, __half* __restrict__ dst)
{
    __shared__ __half t[64][72];           // +8 pad: 16B-conflict-free columns
    const int b  = blockIdx.z;
    const int s0 = blockIdx.x * 64, d0 = blockIdx.y * 64;
    const int tid = threadIdx.x;
    src += (size_t)b * SEQ * DIM;
    dst += (size_t)b * DIM * SEQ;

    // load: 64 rows x 8 float4-chunks (8 halves each)
    #pragma unroll
    for (int q = 0; q < 2; q++) {
        int i = tid + q * 256;
        int row = i >> 3, cp = i & 7;      // cp: 8-half chunk
        uint4 v = *(const uint4*)(src + (size_t)(s0 + row) * DIM + d0 + cp * 8);
        *(uint4*)&t[row][cp * 8] = v;
    }
    __syncthreads();
    // store: 64 d-rows x 8 chunks of 8 s-values
    #pragma unroll
    for (int q = 0; q < 2; q++) {
        int i = tid + q * 256;
        int drow = i >> 3, sp = i & 7;
        __half o[8];
        #pragma unroll
        for (int e = 0; e < 8; e++) o[e] = t[sp * 8 + e][drow];
        *(uint4*)(dst + (size_t)(d0 + drow) * SEQ + s0 + sp * 8) = *(uint4*)o;
    }
}

// ===========================================================================
// Row softmax, in place on fp16 scores (fp32 math in registers)
// ===========================================================================
__global__ __launch_bounds__(256)
void softmax_h16(__half* __restrict__ S)
{
    __shared__ float red_m[8];
    __shared__ float red_s[8];
    const size_t base = (size_t)blockIdx.x * SEQ;
    const int tid  = threadIdx.x;
    const int wid  = tid >> 5;
    const int lane = tid & 31;

    uint4 raw = ((const uint4*)(S + base))[tid];
    __half2 h[4];
    h[0] = *(__half2*)&raw.x; h[1] = *(__half2*)&raw.y;
    h[2] = *(__half2*)&raw.z; h[3] = *(__half2*)&raw.w;
    float v[8];
    #pragma unroll
    for (int i = 0; i < 4; i++) {
        v[2 * i + 0] = __half2float(h[i].x);
        v[2 * i + 1] = __half2float(h[i].y);
    }

    float m = v[0];
    #pragma unroll
    for (int i = 1; i < 8; i++) m = fmaxf(m, v[i]);
    #pragma unroll
    for (int o = 16; o > 0; o >>= 1) m = fmaxf(m, __shfl_xor_sync(~0u, m, o));
    if (lane == 0) red_m[wid] = m;
    __syncthreads();
    m = red_m[0];
    #pragma unroll
    for (int i = 1; i < 8; i++) m = fmaxf(m, red_m[i]);

    float s = 0.f;
    #pragma unroll
    for (int i = 0; i < 8; i++) { v[i] = __expf(v[i] - m); s += v[i]; }
    #pragma unroll
    for (int o = 16; o > 0; o >>= 1) s += __shfl_xor_sync(~0u, s, o);
    if (lane == 0) red_s[wid] = s;
    __syncthreads();
    s = red_s[0];
    #pragma unroll
    for (int i = 1; i < 8; i++) s += red_s[i];
    const float inv = 1.f / s;

    #pragma unroll
    for (int i = 0; i < 4; i++) {
        h[i].x = __float2half(v[2 * i + 0] * inv);
        h[i].y = __float2half(v[2 * i + 1] * inv);
    }
    uint4 outw;
    outw.x = *(uint32_t*)&h[0]; outw.y = *(uint32_t*)&h[1];
    outw.z = *(uint32_t*)&h[2]; outw.w = *(uint32_t*)&h[3];
    ((uint4*)(S + base))[tid] = outw;
}

// ===========================================================================
extern "C" void kernel_launch(void* const* d_in, const int* in_sizes, int n_in,
                              void* d_out, int out_size)
{
    const float* x  = (const float*)d_in[0];
    const float* Wq = (const float*)d_in[1];
    const float* Wk = (const float*)d_in[2];
    const float* Wv = (const float*)d_in[3];
    float* out = (float*)d_out;

    cudaFuncSetAttribute(hgemm1, cudaFuncAttributeMaxDynamicSharedMemorySize, SMEM_GEMM);

    unsigned char* base;
    cudaGetSymbolAddress((void**)&base, g_scratch);

    __half* xh   = (__half*)(base + O_XH);
    __half* wh   = (__half*)(base + O_WH);
    __half* qkvh = (__half*)(base + O_QKVH);
    __half* vt   = (__half*)(base + O_VT);
    __half* sh   = (__half*)(base + O_SH);

    const float scale = 0.044194173824159216f;   // 1/sqrt(512)

    // launch 0: convert x + Wq + Wk + Wv to fp16 (single fused launch)
    cvt_all<<<(unsigned)(CVT_TOTAL4 / 512), 256>>>(x, Wq, Wk, Wv, xh, wh);

    // launch 1: QKV projections, fp16 epilogue (grid.z batches the 3 weights)
    {
        dim3 g(DIM / 128, MTOT / 128, 3);
        hgemm1<<<g, 256, SMEM_GEMM>>>(xh, wh, nullptr, qkvh,
                                      DIM, DIM, DIM, DIM / 64,
                                      0, (size_t)DIM * DIM, SZ_X, 1.0f);
    }

    // launch 2: transpose V -> V^T
    {
        dim3 g(SEQ / 64, DIM / 64, BATCH);
        transpose_h<<<g, 256>>>(qkvh + 2 * SZ_X, vt);
    }

    // launch 3: scores = Q @ K^T * scale, written directly as fp16
    {
        dim3 g(SEQ / 128, SEQ / 128, BATCH);
        hgemm1<<<g, 256, SMEM_GEMM>>>(qkvh, qkvh + SZ_X, nullptr, sh,
                                      DIM, DIM, SEQ, DIM / 64,
                                      (size_t)SEQ * DIM, (size_t)SEQ * DIM,
                                      (size_t)SEQ * SEQ, scale);
    }

    // launch 4: softmax in place on fp16 scores
    softmax_h16<<<BATCH * SEQ, 256>>>(sh);

    // launch 5: out = attn @ V  (fp32 epilogue)  <- ncu -s 5 -c 1 target
    {
        dim3 g(DIM / 128, SEQ / 128, BATCH);
        hgemm1<<<g, 256, SMEM_GEMM>>>(sh, vt, out, nullptr,
                                      SEQ, SEQ, DIM, SEQ / 64,
                                      (size_t)SEQ * SEQ, (size_t)DIM * SEQ,
                                      (size_t)SEQ * DIM, 1.0f);
    }
}

// round 17
// speedup vs baseline: 1.0304x; 1.0171x over previous
#include <cuda_runtime.h>
#include <cuda_fp16.h>
#include <math.h>
#include <stdint.h>

#define BATCH 8
#define SEQ   2048
#define DIM   512
#define MTOT  (BATCH*SEQ)        // 16384

// ===========================================================================
// Scratch memory (single __device__ array; no allocation anywhere)
// ===========================================================================
#define SZ_X ((size_t)MTOT * DIM)                     // 8,388,608 elems
static const size_t O_XH   = 0;                                 // fp16 SZ_X
static const size_t O_WH   = O_XH  + SZ_X * 2;                  // fp16 3*DIM*DIM
static const size_t O_QKVH = O_WH  + (size_t)3 * DIM * DIM * 2; // fp16 3*SZ_X
static const size_t O_VT   = O_QKVH + (size_t)3 * SZ_X * 2;     // fp16 SZ_X (V^T)
static const size_t O_SH   = O_VT  + SZ_X * 2;                  // fp16 B*S*S
static const size_t SCRATCH_TOTAL = O_SH + (size_t)BATCH * SEQ * SEQ * 2;

__device__ __align__(1024) unsigned char g_scratch[SCRATCH_TOTAL];

// ===========================================================================
// PTX helpers (arch-agnostic: cp.async / ldmatrix / mma.sync only)
// ===========================================================================
__device__ __forceinline__ uint32_t smem_u32(const void* p) {
    uint32_t a;
    asm("{ .reg .u64 t; cvta.to.shared.u64 t, %1; cvt.u32.u64 %0, t; }"
        : "=r"(a) : "l"(p));
    return a;
}

#define SWZ128(x) ((x) ^ (((x) >> 3) & 0x70))

__device__ __forceinline__ void cp16(uint32_t dst, const void* src) {
    asm volatile("cp.async.cg.shared.global [%0], [%1], 16;\n"
                 :: "r"(dst), "l"(src));
}
__device__ __forceinline__ void cp_commit() {
    asm volatile("cp.async.commit_group;\n" ::: "memory");
}
template <int N> __device__ __forceinline__ void cp_wait() {
    asm volatile("cp.async.wait_group %0;\n" :: "n"(N) : "memory");
}

__device__ __forceinline__ void ldm_x4(uint32_t* r, uint32_t addr) {
    asm volatile("ldmatrix.sync.aligned.m8n8.x4.shared.b16 {%0,%1,%2,%3}, [%4];"
                 : "=r"(r[0]), "=r"(r[1]), "=r"(r[2]), "=r"(r[3]) : "r"(addr));
}

__device__ __forceinline__ void mma_f16(float* c, const uint32_t* a,
                                        uint32_t b0, uint32_t b1) {
    asm volatile("mma.sync.aligned.m16n8k16.row.col.f32.f16.f16.f32 "
                 "{%0,%1,%2,%3}, {%4,%5,%6,%7}, {%8,%9}, {%0,%1,%2,%3};"
                 : "+f"(c[0]), "+f"(c[1]), "+f"(c[2]), "+f"(c[3])
                 : "r"(a[0]), "r"(a[1]), "r"(a[2]), "r"(a[3]), "r"(b0), "r"(b1));
}

// ===========================================================================
// Single-term HMMA GEMM:  C = alpha * A@B^T   (fp16 NT, fp32 accum)
// CTA 128x128, BK=64, 256 threads, 8 warps x (32M x 64N) tiles,
// 3-stage cp.async pipeline (3 x 32 KB), ONE barrier per k-iter, 2 CTAs/SM.
// (R12 champion configuration, verbatim.)
// Epilogue: fp32*alpha if Ch==null, else fp16 (alpha applied).
// ===========================================================================
#define ST_BYTES 32768u
#define SMEM_GEMM (3 * 32768 + 1024)

__global__ __launch_bounds__(256, 2)
void hgemm1(const __half* __restrict__ A,
            const __half* __restrict__ B,
            float* __restrict__ C,
            __half* __restrict__ Ch,
            int ldA, int ldB, int ldC, int kTiles,
            size_t sA, size_t sB, size_t sC, float alpha)
{
    extern __shared__ char smem_raw[];
    const uint32_t sbase = (smem_u32(smem_raw) + 1023u) & ~1023u;

    const int tid  = threadIdx.x;
    const int wid  = tid >> 5;
    const int lane = tid & 31;
    const int wm   = wid & 3;      // 4 M-warps -> 32 rows each
    const int wn   = wid >> 2;     // 2 N-warps -> 64 cols each

    const int row0 = blockIdx.y * 128;
    const int col0 = blockIdx.x * 128;

    A += (size_t)blockIdx.z * sA;
    B += (size_t)blockIdx.z * sB;

    float acc[2][8][4];
    #pragma unroll
    for (int mt = 0; mt < 2; mt++)
        #pragma unroll
        for (int j = 0; j < 8; j++)
            #pragma unroll
            for (int q = 0; q < 4; q++) acc[mt][j][q] = 0.f;

    auto load_stage = [&](int t) {
        const int kk = t * 64;
        const uint32_t st = sbase + (uint32_t)(t % 3) * ST_BYTES;
        #pragma unroll
        for (int q = 0; q < 4; q++) {
            int idx = tid + q * 256;
            int rr = idx >> 3, cc = idx & 7;
            uint32_t d = SWZ128((uint32_t)(rr * 128 + cc * 16));
            cp16(st +          d, A + (size_t)(row0 + rr) * ldA + kk + cc * 8);
            cp16(st + 16384u + d, B + (size_t)(col0 + rr) * ldB + kk + cc * 8);
        }
        cp_commit();
    };

    load_stage(0);
    if (kTiles > 1) load_stage(1);

    const uint32_t lrow = (uint32_t)(lane & 15);
    const uint32_t lcol = (uint32_t)((lane >> 4) * 16);

    for (int t = 0; t < kTiles; t++) {
        if (t + 1 < kTiles) cp_wait<1>(); else cp_wait<0>();
        __syncthreads();
        // stage t resident; buffer (t+2)%3 free (compute t-1 done by barrier)
        if (t + 2 < kTiles) load_stage(t + 2);

        const uint32_t st = sbase + (uint32_t)(t % 3) * ST_BYTES;
        const uint32_t As = st;
        const uint32_t Bs = st + 16384u;

        #pragma unroll
        for (int k16 = 0; k16 < 4; k16++) {
            const uint32_t koff = (uint32_t)(k16 * 32) + lcol;
            uint32_t a[2][4];
            #pragma unroll
            for (int mt = 0; mt < 2; mt++)
                ldm_x4(a[mt], As + SWZ128((uint32_t)((wm * 32 + mt * 16 + lrow) * 128) + koff));
            uint32_t b[4][4];
            #pragma unroll
            for (int ng = 0; ng < 4; ng++)
                ldm_x4(b[ng], Bs + SWZ128((uint32_t)((wn * 64 + ng * 16 + lrow) * 128) + koff));
            #pragma unroll
            for (int mt = 0; mt < 2; mt++)
                #pragma unroll
                for (int j = 0; j < 8; j++) {
                    const int ng = j >> 1;
                    mma_f16(acc[mt][j], a[mt], b[ng][(j & 1) ? 1 : 0], b[ng][(j & 1) ? 3 : 2]);
                }
        }
    }

    const int er = lane >> 2;
    const int ec = (lane & 3) * 2;
    if (Ch) {
        Ch += (size_t)blockIdx.z * sC;
        #pragma unroll
        for (int mt = 0; mt < 2; mt++) {
            const int rb = row0 + wm * 32 + mt * 16 + er;
            #pragma unroll
            for (int j = 0; j < 8; j++) {
                const int cb = col0 + wn * 64 + j * 8 + ec;
                __half2 H0, H1;
                H0.x = __float2half(alpha * acc[mt][j][0]);
                H0.y = __float2half(alpha * acc[mt][j][1]);
                H1.x = __float2half(alpha * acc[mt][j][2]);
                H1.y = __float2half(alpha * acc[mt][j][3]);
                *(__half2*)(Ch + (size_t)rb * ldC + cb)       = H0;
                *(__half2*)(Ch + (size_t)(rb + 8) * ldC + cb) = H1;
            }
        }
    } else {
        C += (size_t)blockIdx.z * sC;
        #pragma unroll
        for (int mt = 0; mt < 2; mt++) {
            const int rb = row0 + wm * 32 + mt * 16 + er;
            #pragma unroll
            for (int j = 0; j < 8; j++) {
                const int cb = col0 + wn * 64 + j * 8 + ec;
                *(float2*)(C + (size_t)rb * ldC + cb) =
                    make_float2(alpha * acc[mt][j][0], alpha * acc[mt][j][1]);
                *(float2*)(C + (size_t)(rb + 8) * ldC + cb) =
                    make_float2(alpha * acc[mt][j][2], alpha * acc[mt][j][3]);
            }
        }
    }
}

// ===========================================================================
// Fused fp32 -> fp16 convert for x and the 3 weight matrices (ONE launch).
// ===========================================================================
#define NX4 (SZ_X / 4)                     // 2,097,152 float4's of x
#define W4  ((size_t)DIM * DIM / 4)        // 65,536 float4's per weight

__global__ __launch_bounds__(256)
void cvt_all(const float* __restrict__ x,
             const float* __restrict__ Wq,
             const float* __restrict__ Wk,
             const float* __restrict__ Wv,
             __half* __restrict__ xh, __half* __restrict__ wh)
{
    size_t i = (size_t)blockIdx.x * 256 + threadIdx.x;
    const float* src;
    __half* dst;
    size_t off;
    if (i < NX4) {
        src = x;  dst = xh;  off = i;
    } else {
        size_t j = i - NX4;
        size_t w = j / W4;
        off = j - w * W4;
        src = (w == 0) ? Wq : (w == 1) ? Wk : Wv;
        dst = wh + w * DIM * DIM;
    }
    float4 v = ((const float4*)src)[off];
    __half2 H0, H1;
    H0.x = __float2half(v.x); H0.y = __float2half(v.y);
    H1.x = __float2half(v.z); H1.y = __float2half(v.w);
    ((__half2*)dst)[2 * off + 0] = H0;
    ((__half2*)dst)[2 * off + 1] = H1;
}

// ===========================================================================
// fp16 [b,s,d] -> fp16 [b,d,s] transpose (64x64 tiles), grid.z = batch
// ===========================================================================
__global__ __launch_bounds__(256)
void transpose_h(const __half* __restrict__ src, __half* __restrict__ dst)
{
    __shared__ __half t[64][65];
    const int b  = blockIdx.z;
    const int s0 = blockIdx.x * 64, d0 = blockIdx.y * 64;
    const int tid = threadIdx.x;
    src += (size_t)b * SEQ * DIM;
    dst += (size_t)b * DIM * SEQ;

    #pragma unroll
    for (int q = 0; q < 8; q++) {
        int i = tid + q * 256;
        int row = i >> 5, cp = i & 31;
        __half2 v = *(const __half2*)(src + (size_t)(s0 + row) * DIM + d0 + cp * 2);
        t[row][cp * 2 + 0] = v.x;
        t[row][cp * 2 + 1] = v.y;
    }
    __syncthreads();
    #pragma unroll
    for (int q = 0; q < 8; q++) {
        int i = tid + q * 256;
        int drow = i >> 5, sp = i & 31;
        __half2 o;
        o.x = t[sp * 2 + 0][drow];
        o.y = t[sp * 2 + 1][drow];
        *(__half2*)(dst + (size_t)(d0 + drow) * SEQ + s0 + sp * 2) = o;
    }
}

// ===========================================================================
// Row softmax, in place on fp16 scores (fp32 math in registers)
// ===========================================================================
__global__ __launch_bounds__(256)
void softmax_h16(__half* __restrict__ S)
{
    __shared__ float red_m[8];
    __shared__ float red_s[8];
    const size_t base = (size_t)blockIdx.x * SEQ;
    const int tid  = threadIdx.x;
    const int wid  = tid >> 5;
    const int lane = tid & 31;

    uint4 raw = ((const uint4*)(S + base))[tid];
    __half2 h[4];
    h[0] = *(__half2*)&raw.x; h[1] = *(__half2*)&raw.y;
    h[2] = *(__half2*)&raw.z; h[3] = *(__half2*)&raw.w;
    float v[8];
    #pragma unroll
    for (int i = 0; i < 4; i++) {
        v[2 * i + 0] = __half2float(h[i].x);
        v[2 * i + 1] = __half2float(h[i].y);
    }

    float m = v[0];
    #pragma unroll
    for (int i = 1; i < 8; i++) m = fmaxf(m, v[i]);
    #pragma unroll
    for (int o = 16; o > 0; o >>= 1) m = fmaxf(m, __shfl_xor_sync(~0u, m, o));
    if (lane == 0) red_m[wid] = m;
    __syncthreads();
    m = red_m[0];
    #pragma unroll
    for (int i = 1; i < 8; i++) m = fmaxf(m, red_m[i]);

    float s = 0.f;
    #pragma unroll
    for (int i = 0; i < 8; i++) { v[i] = __expf(v[i] - m); s += v[i]; }
    #pragma unroll
    for (int o = 16; o > 0; o >>= 1) s += __shfl_xor_sync(~0u, s, o);
    if (lane == 0) red_s[wid] = s;
    __syncthreads();
    s = red_s[0];
    #pragma unroll
    for (int i = 1; i < 8; i++) s += red_s[i];
    const float inv = 1.f / s;

    #pragma unroll
    for (int i = 0; i < 4; i++) {
        h[i].x = __float2half(v[2 * i + 0] * inv);
        h[i].y = __float2half(v[2 * i + 1] * inv);
    }
    uint4 outw;
    outw.x = *(uint32_t*)&h[0]; outw.y = *(uint32_t*)&h[1];
    outw.z = *(uint32_t*)&h[2]; outw.w = *(uint32_t*)&h[3];
    ((uint4*)(S + base))[tid] = outw;
}

// ===========================================================================
extern "C" void kernel_launch(void* const* d_in, const int* in_sizes, int n_in,
                              void* d_out, int out_size)
{
    const float* x  = (const float*)d_in[0];
    const float* Wq = (const float*)d_in[1];
    const float* Wk = (const float*)d_in[2];
    const float* Wv = (const float*)d_in[3];
    float* out = (float*)d_out;

    cudaFuncSetAttribute(hgemm1, cudaFuncAttributeMaxDynamicSharedMemorySize, SMEM_GEMM);

    unsigned char* base;
    cudaGetSymbolAddress((void**)&base, g_scratch);

    __half* xh   = (__half*)(base + O_XH);
    __half* wh   = (__half*)(base + O_WH);
    __half* qkvh = (__half*)(base + O_QKVH);
    __half* vt   = (__half*)(base + O_VT);
    __half* sh   = (__half*)(base + O_SH);

    const float scale = 0.044194173824159216f;   // 1/sqrt(512)

    // launch 0: convert x + Wq + Wk + Wv to fp16 (single fused launch)
    {
        const unsigned total4 = (unsigned)(NX4 + 3 * W4);
        cvt_all<<<total4 / 256, 256>>>(x, Wq, Wk, Wv, xh, wh);
    }

    // launch 1: QKV projections, fp16 epilogue (grid.z batches the 3 weights)
    {
        dim3 g(DIM / 128, MTOT / 128, 3);
        hgemm1<<<g, 256, SMEM_GEMM>>>(xh, wh, nullptr, qkvh,
                                      DIM, DIM, DIM, DIM / 64,
                                      0, (size_t)DIM * DIM, SZ_X, 1.0f);
    }

    // launch 2: transpose V -> V^T
    {
        dim3 g(SEQ / 64, DIM / 64, BATCH);
        transpose_h<<<g, 256>>>(qkvh + 2 * SZ_X, vt);
    }

    // launch 3: scores = Q @ K^T * scale, written directly as fp16
    {
        dim3 g(SEQ / 128, SEQ / 128, BATCH);
        hgemm1<<<g, 256, SMEM_GEMM>>>(qkvh, qkvh + SZ_X, nullptr, sh,
                                      DIM, DIM, SEQ, DIM / 64,
                                      (size_t)SEQ * DIM, (size_t)SEQ * DIM,
                                      (size_t)SEQ * SEQ, scale);
    }

    // launch 4: softmax in place on fp16 scores
    softmax_h16<<<BATCH * SEQ, 256>>>(sh);

    // launch 5: out = attn @ V  (fp32 epilogue)
    {
        dim3 g(DIM / 128, SEQ / 128, BATCH);
        hgemm1<<<g, 256, SMEM_GEMM>>>(sh, vt, out, nullptr,
                                      SEQ, SEQ, DIM, SEQ / 64,
                                      (size_t)SEQ * SEQ, (size_t)DIM * SEQ,
                                      (size_t)SEQ * DIM, 1.0f);
    }
}